// round 1
// baseline (speedup 1.0000x reference)
#include <cuda_runtime.h>

#define SB   2
#define SS   2048
#define SH   16
#define SD   64
#define SDM  1024
#define MTOT (SB * SS)   // 4096

// Scratch (allocations are forbidden; use device globals).
__device__ float g_Q[SB * SH * SS * SD];   // [B,H,S,D]
__device__ float g_K[SB * SH * SS * SD];
__device__ float g_V[SB * SH * SS * SD];
__device__ float g_A[MTOT * SDM];          // attn out, [B,S,H,D] == [4096,1024]

// ---------------------------------------------------------------------------
// Kernel 1: per-head QKV projection.
// grid = (MTOT/64, 48); z = which*16 + h. C[64x64] tile, K=1024, BK=16.
// ---------------------------------------------------------------------------
__global__ __launch_bounds__(256) void qkv_gemm(
    const float* __restrict__ x,
    const float* __restrict__ Wq, const float* __restrict__ bq,
    const float* __restrict__ Wk, const float* __restrict__ bk,
    const float* __restrict__ Wv, const float* __restrict__ bv)
{
    __shared__ float As[16 * 68];   // A transposed: As[k][m], pad 68
    __shared__ float Bs[16 * 68];   // Bs[k][n], pad 68

    const int z     = blockIdx.y;
    const int which = z >> 4;
    const int h     = z & 15;

    const float* W;  const float* bias;  float* obase;
    if (which == 0)      { W = Wq; bias = bq; obase = g_Q; }
    else if (which == 1) { W = Wk; bias = bk; obase = g_K; }
    else                 { W = Wv; bias = bv; obase = g_V; }
    const float* Wh = W + h * SDM * SD;

    const int m0  = blockIdx.x * 64;
    const int tid = threadIdx.x;
    const int tx  = tid & 15, ty = tid >> 4;
    const int ty4 = ty * 4, tx4 = tx * 4;
    // loader indices
    const int ar = tid >> 2;           // 0..63  (A row within tile)
    const int ak = (tid & 3) << 2;     // 0,4,8,12
    const int br = tid >> 4;           // 0..15  (B row = k)
    const int bn = (tid & 15) << 2;    // 0..60

    float acc[4][4];
    #pragma unroll
    for (int i = 0; i < 4; i++)
        #pragma unroll
        for (int j = 0; j < 4; j++) acc[i][j] = 0.f;

    for (int k0 = 0; k0 < SDM; k0 += 16) {
        float4 av = *(const float4*)(x + (m0 + ar) * SDM + k0 + ak);
        float4 bv4 = *(const float4*)(Wh + (k0 + br) * SD + bn);
        __syncthreads();
        As[(ak + 0) * 68 + ar] = av.x;
        As[(ak + 1) * 68 + ar] = av.y;
        As[(ak + 2) * 68 + ar] = av.z;
        As[(ak + 3) * 68 + ar] = av.w;
        *(float4*)(Bs + br * 68 + bn) = bv4;
        __syncthreads();
        #pragma unroll
        for (int k = 0; k < 16; k++) {
            float4 a4 = *(const float4*)(As + k * 68 + ty4);
            float4 b4 = *(const float4*)(Bs + k * 68 + tx4);
            float a[4] = {a4.x, a4.y, a4.z, a4.w};
            float b[4] = {b4.x, b4.y, b4.z, b4.w};
            #pragma unroll
            for (int i = 0; i < 4; i++)
                #pragma unroll
                for (int j = 0; j < 4; j++) acc[i][j] += a[i] * b[j];
        }
    }

    // write to [B,H,S,D]
    #pragma unroll
    for (int i = 0; i < 4; i++) {
        const int m  = m0 + ty4 + i;
        const int bb = m >> 11;         // /2048
        const int s  = m & 2047;
        float4 o;
        o.x = acc[i][0] + bias[h * SD + tx4 + 0];
        o.y = acc[i][1] + bias[h * SD + tx4 + 1];
        o.z = acc[i][2] + bias[h * SD + tx4 + 2];
        o.w = acc[i][3] + bias[h * SD + tx4 + 3];
        *(float4*)(obase + ((bb * SH + h) * SS + s) * SD + tx4) = o;
    }
}

// ---------------------------------------------------------------------------
// Kernel 2: flash attention, fp32, online softmax.
// grid = (SS/64, B*H); block 256 = 16x16 threads, 4x4 micro-tiles.
// dynamic smem: sQT[64][68] + sKT[64][68] + sV[64][64] + sP[64][64]
// ---------------------------------------------------------------------------
__global__ __launch_bounds__(256) void attn_kernel()
{
    extern __shared__ float sm[];
    float* sQT = sm;                  // d-major, pad 68
    float* sKT = sQT + 64 * 68;       // d-major, pad 68
    float* sV  = sKT + 64 * 68;       // [t][d], stride 64
    float* sP  = sV + 64 * 64;        // [q][k], stride 64

    const int bh = blockIdx.y;
    const int q0 = blockIdx.x * 64;
    const float* Qp = g_Q + bh * SS * SD;
    const float* Kp = g_K + bh * SS * SD;
    const float* Vp = g_V + bh * SS * SD;

    const int tid = threadIdx.x;
    const int tx  = tid & 15, ty = tid >> 4;
    const int ty4 = ty * 4, tx4 = tx * 4;

    // load Q tile transposed + pre-scaled by 1/sqrt(D)
    for (int i = tid; i < 1024; i += 256) {
        const int q = i >> 4, d4 = (i & 15) << 2;
        float4 v = *(const float4*)(Qp + (q0 + q) * SD + d4);
        sQT[(d4 + 0) * 68 + q] = v.x * 0.125f;
        sQT[(d4 + 1) * 68 + q] = v.y * 0.125f;
        sQT[(d4 + 2) * 68 + q] = v.z * 0.125f;
        sQT[(d4 + 3) * 68 + q] = v.w * 0.125f;
    }

    float m_i[4], l_i[4], acc[4][4];
    #pragma unroll
    for (int i = 0; i < 4; i++) {
        m_i[i] = -1e30f; l_i[i] = 0.f;
        #pragma unroll
        for (int j = 0; j < 4; j++) acc[i][j] = 0.f;
    }

    for (int t0 = 0; t0 < SS; t0 += 64) {
        __syncthreads();   // previous iteration fully done (incl. P·V reads)
        for (int i = tid; i < 1024; i += 256) {
            const int t = i >> 4, d4 = (i & 15) << 2;
            float4 kv = *(const float4*)(Kp + (t0 + t) * SD + d4);
            sKT[(d4 + 0) * 68 + t] = kv.x;
            sKT[(d4 + 1) * 68 + t] = kv.y;
            sKT[(d4 + 2) * 68 + t] = kv.z;
            sKT[(d4 + 3) * 68 + t] = kv.w;
            *(float4*)(sV + t * SD + d4) = *(const float4*)(Vp + (t0 + t) * SD + d4);
        }
        __syncthreads();

        // scores S = (Q/sqrt(D)) . K^T, 4x4 per thread
        float sc[4][4];
        #pragma unroll
        for (int i = 0; i < 4; i++)
            #pragma unroll
            for (int j = 0; j < 4; j++) sc[i][j] = 0.f;

        #pragma unroll
        for (int d = 0; d < 64; d += 4) {
            float a[4][4], b[4][4];
            #pragma unroll
            for (int r = 0; r < 4; r++) {
                float4 a4 = *(const float4*)(sQT + (d + r) * 68 + ty4);
                a[r][0] = a4.x; a[r][1] = a4.y; a[r][2] = a4.z; a[r][3] = a4.w;
                float4 b4 = *(const float4*)(sKT + (d + r) * 68 + tx4);
                b[r][0] = b4.x; b[r][1] = b4.y; b[r][2] = b4.z; b[r][3] = b4.w;
            }
            #pragma unroll
            for (int r = 0; r < 4; r++)
                #pragma unroll
                for (int i = 0; i < 4; i++)
                    #pragma unroll
                    for (int j = 0; j < 4; j++) sc[i][j] += a[r][i] * b[r][j];
        }

        // online softmax per query row (rows split by ty, cols by tx; reduce over tx)
        #pragma unroll
        for (int i = 0; i < 4; i++) {
            float mx = fmaxf(fmaxf(sc[i][0], sc[i][1]), fmaxf(sc[i][2], sc[i][3]));
            #pragma unroll
            for (int off = 8; off; off >>= 1)
                mx = fmaxf(mx, __shfl_xor_sync(0xffffffffu, mx, off, 16));
            const float mn   = fmaxf(m_i[i], mx);
            const float corr = __expf(m_i[i] - mn);
            m_i[i] = mn;
            float rs = 0.f;
            #pragma unroll
            for (int j = 0; j < 4; j++) { sc[i][j] = __expf(sc[i][j] - mn); rs += sc[i][j]; }
            #pragma unroll
            for (int off = 8; off; off >>= 1)
                rs += __shfl_xor_sync(0xffffffffu, rs, off, 16);
            l_i[i] = l_i[i] * corr + rs;
            #pragma unroll
            for (int j = 0; j < 4; j++) acc[i][j] *= corr;
            float4 p4; p4.x = sc[i][0]; p4.y = sc[i][1]; p4.z = sc[i][2]; p4.w = sc[i][3];
            *(float4*)(sP + (ty4 + i) * SD + tx4) = p4;
        }
        __syncthreads();

        // O += P . V
        #pragma unroll
        for (int k = 0; k < 64; k += 4) {
            float p[4][4], v[4][4];
            #pragma unroll
            for (int i = 0; i < 4; i++) {
                float4 p4 = *(const float4*)(sP + (ty4 + i) * SD + k);
                p[i][0] = p4.x; p[i][1] = p4.y; p[i][2] = p4.z; p[i][3] = p4.w;
            }
            #pragma unroll
            for (int r = 0; r < 4; r++) {
                float4 v4 = *(const float4*)(sV + (k + r) * SD + tx4);
                v[r][0] = v4.x; v[r][1] = v4.y; v[r][2] = v4.z; v[r][3] = v4.w;
            }
            #pragma unroll
            for (int i = 0; i < 4; i++)
                #pragma unroll
                for (int j = 0; j < 4; j++)
                    acc[i][j] += p[i][0] * v[0][j] + p[i][1] * v[1][j]
                               + p[i][2] * v[2][j] + p[i][3] * v[3][j];
        }
    }

    // epilogue: normalize, write [B,S,H,D]
    const int bb = bh >> 4, h = bh & 15;
    #pragma unroll
    for (int i = 0; i < 4; i++) {
        const float inv = 1.f / l_i[i];
        const int s = q0 + ty4 + i;
        float4 o;
        o.x = acc[i][0] * inv; o.y = acc[i][1] * inv;
        o.z = acc[i][2] * inv; o.w = acc[i][3] * inv;
        *(float4*)(g_A + ((bb * SS + s) * SH + h) * SD + tx4) = o;
    }
}

// ---------------------------------------------------------------------------
// Kernel 3: output projection [4096,1024] @ [1024,1024] + bias
// grid = (MTOT/64, SDM/64)
// ---------------------------------------------------------------------------
__global__ __launch_bounds__(256) void proj_gemm(
    const float* __restrict__ Wo, const float* __restrict__ bo,
    float* __restrict__ out)
{
    __shared__ float As[16 * 68];
    __shared__ float Bs[16 * 68];

    const int m0 = blockIdx.x * 64;
    const int n0 = blockIdx.y * 64;
    const int tid = threadIdx.x;
    const int tx = tid & 15, ty = tid >> 4;
    const int ty4 = ty * 4, tx4 = tx * 4;
    const int ar = tid >> 2;
    const int ak = (tid & 3) << 2;
    const int br = tid >> 4;
    const int bn = (tid & 15) << 2;

    float acc[4][4];
    #pragma unroll
    for (int i = 0; i < 4; i++)
        #pragma unroll
        for (int j = 0; j < 4; j++) acc[i][j] = 0.f;

    for (int k0 = 0; k0 < SDM; k0 += 16) {
        float4 av = *(const float4*)(g_A + (m0 + ar) * SDM + k0 + ak);
        float4 bv4 = *(const float4*)(Wo + (k0 + br) * SDM + n0 + bn);
        __syncthreads();
        As[(ak + 0) * 68 + ar] = av.x;
        As[(ak + 1) * 68 + ar] = av.y;
        As[(ak + 2) * 68 + ar] = av.z;
        As[(ak + 3) * 68 + ar] = av.w;
        *(float4*)(Bs + br * 68 + bn) = bv4;
        __syncthreads();
        #pragma unroll
        for (int k = 0; k < 16; k++) {
            float4 a4 = *(const float4*)(As + k * 68 + ty4);
            float4 b4 = *(const float4*)(Bs + k * 68 + tx4);
            float a[4] = {a4.x, a4.y, a4.z, a4.w};
            float b[4] = {b4.x, b4.y, b4.z, b4.w};
            #pragma unroll
            for (int i = 0; i < 4; i++)
                #pragma unroll
                for (int j = 0; j < 4; j++) acc[i][j] += a[i] * b[j];
        }
    }

    #pragma unroll
    for (int i = 0; i < 4; i++) {
        const int m = m0 + ty4 + i;
        float4 o;
        o.x = acc[i][0] + bo[n0 + tx4 + 0];
        o.y = acc[i][1] + bo[n0 + tx4 + 1];
        o.z = acc[i][2] + bo[n0 + tx4 + 2];
        o.w = acc[i][3] + bo[n0 + tx4 + 3];
        *(float4*)(out + m * SDM + n0 + tx4) = o;
    }
}

// ---------------------------------------------------------------------------
extern "C" void kernel_launch(void* const* d_in, const int* in_sizes, int n_in,
                              void* d_out, int out_size)
{
    const float* x  = (const float*)d_in[0];
    const float* Wq = (const float*)d_in[1];
    const float* bq = (const float*)d_in[2];
    const float* Wk = (const float*)d_in[3];
    const float* bk = (const float*)d_in[4];
    const float* Wv = (const float*)d_in[5];
    const float* bv = (const float*)d_in[6];
    const float* Wo = (const float*)d_in[7];
    const float* bo = (const float*)d_in[8];
    float* out = (float*)d_out;

    qkv_gemm<<<dim3(MTOT / 64, 48), 256>>>(x, Wq, bq, Wk, bk, Wv, bv);

    const int attn_smem = (2 * 64 * 68 + 2 * 64 * 64) * (int)sizeof(float); // 67584 B
    cudaFuncSetAttribute(attn_kernel, cudaFuncAttributeMaxDynamicSharedMemorySize, attn_smem);
    attn_kernel<<<dim3(SS / 64, SB * SH), 256, attn_smem>>>();

    proj_gemm<<<dim3(MTOT / 64, SDM / 64), 256>>>(Wo, bo, out);
}

// round 3
// speedup vs baseline: 1.3076x; 1.3076x over previous
#include <cuda_runtime.h>
#include <cuda_bf16.h>
#include <cstdint>

#define SB   2
#define SS   2048
#define SH   16
#define SD   64
#define SDM  1024
#define MTOT (SB * SS)   // 4096
#define NQKV 3072
#define K3   3072        // concatenated split-K
#define KITER 48         // K3 / 64

// ------------------------- device scratch (no allocs) -----------------------
__device__ float g_Q[SB * SH * SS * SD];   // [B,H,S,D] fp32
__device__ float g_K[SB * SH * SS * SD];
__device__ float g_V[SB * SH * SS * SD];
__device__ float g_A[MTOT * SDM];          // attention out [B,S,H*D] fp32

__device__ __nv_bfloat16 g_X2[MTOT * K3];     // [m][k']: hi|hi|lo
__device__ __nv_bfloat16 g_A2[MTOT * K3];     // [m][k']: hi|hi|lo
__device__ __nv_bfloat16 g_B2qkv[NQKV * K3];  // [n][k']: hi|lo|hi
__device__ __nv_bfloat16 g_B2o[SDM * K3];     // [n][k']: hi|lo|hi
__device__ float g_bias_qkv[NQKV];

// ------------------------------ PTX helpers ---------------------------------
__device__ __forceinline__ uint32_t smem_u32(const void* p) {
    uint32_t a;
    asm("{ .reg .u64 t; cvta.to.shared.u64 t, %1; cvt.u32.u64 %0, t; }" : "=r"(a) : "l"(p));
    return a;
}
__device__ __forceinline__ void cp16(uint32_t dst, const void* src) {
    asm volatile("cp.async.cg.shared.global [%0], [%1], 16;" :: "r"(dst), "l"(src));
}
#define CP_COMMIT() asm volatile("cp.async.commit_group;" ::: "memory")

__device__ __forceinline__ void ldmx4(uint32_t* r, uint32_t addr) {
    asm volatile("ldmatrix.sync.aligned.m8n8.x4.shared.b16 {%0,%1,%2,%3}, [%4];"
        : "=r"(r[0]), "=r"(r[1]), "=r"(r[2]), "=r"(r[3]) : "r"(addr));
}
__device__ __forceinline__ void mma16816(float* c, const uint32_t* a, const uint32_t* b) {
    asm volatile(
        "mma.sync.aligned.m16n8k16.row.col.f32.bf16.bf16.f32 "
        "{%0,%1,%2,%3}, {%4,%5,%6,%7}, {%8,%9}, {%0,%1,%2,%3};"
        : "+f"(c[0]), "+f"(c[1]), "+f"(c[2]), "+f"(c[3])
        : "r"(a[0]), "r"(a[1]), "r"(a[2]), "r"(a[3]), "r"(b[0]), "r"(b[1]));
}

// ----------------------------- conversion kernels ---------------------------
// A-side split: dst[m][k]=hi, dst[m][1024+k]=hi, dst[m][2048+k]=lo
__global__ void conv_split2(const float* __restrict__ src, __nv_bfloat16* __restrict__ dst)
{
    const int n = MTOT * SDM;
    for (int i = blockIdx.x * blockDim.x + threadIdx.x; i < n; i += gridDim.x * blockDim.x) {
        const int m = i >> 10, k = i & 1023;
        float v = src[i];
        __nv_bfloat16 hi = __float2bfloat16(v);
        __nv_bfloat16 lo = __float2bfloat16(v - __bfloat162float(hi));
        const size_t base = (size_t)m * K3;
        dst[base + k] = hi;
        dst[base + 1024 + k] = hi;
        dst[base + 2048 + k] = lo;
    }
}

// B-side split: dst[n][k]=hi, dst[n][1024+k]=lo, dst[n][2048+k]=hi
__global__ void conv_wqkv2(const float* __restrict__ Wq, const float* __restrict__ bq,
                           const float* __restrict__ Wk, const float* __restrict__ bk,
                           const float* __restrict__ Wv, const float* __restrict__ bv)
{
    const int n_el = NQKV * SDM;
    for (int i = blockIdx.x * blockDim.x + threadIdx.x; i < n_el; i += gridDim.x * blockDim.x) {
        const int n = i >> 10, k = i & 1023;
        const int which = n >> 10, h = (n >> 6) & 15, d = n & 63;
        const float* W = (which == 0) ? Wq : (which == 1) ? Wk : Wv;
        float v = W[((size_t)h * SDM + k) * SD + d];
        __nv_bfloat16 hi = __float2bfloat16(v);
        __nv_bfloat16 lo = __float2bfloat16(v - __bfloat162float(hi));
        const size_t base = (size_t)n * K3;
        g_B2qkv[base + k] = hi;
        g_B2qkv[base + 1024 + k] = lo;
        g_B2qkv[base + 2048 + k] = hi;
        if (k == 0) {
            const float* bb = (which == 0) ? bq : (which == 1) ? bk : bv;
            g_bias_qkv[n] = bb[h * SD + d];
        }
    }
}

__global__ void conv_wo2(const float* __restrict__ Wo)
{
    const int n_el = SDM * SDM;
    for (int i = blockIdx.x * blockDim.x + threadIdx.x; i < n_el; i += gridDim.x * blockDim.x) {
        const int n = i >> 10, k = i & 1023;
        float v = Wo[(size_t)k * SDM + n];
        __nv_bfloat16 hi = __float2bfloat16(v);
        __nv_bfloat16 lo = __float2bfloat16(v - __bfloat162float(hi));
        const size_t base = (size_t)n * K3;
        g_B2o[base + k] = hi;
        g_B2o[base + 1024 + k] = lo;
        g_B2o[base + 2048 + k] = hi;
    }
}

// ------------------------- bf16 mma.sync GEMM -------------------------------
// C[M, N] = A2[M, K3] * B2[N, K3]^T (+ bias[n])
// CTA 128x128, BK=64, 256 threads = 8 warps (2 m x 4 n), warp = 64x32.
// mode 0: scatter rows/cols to g_Q/g_K/g_V [B,H,S,D]; mode 1: outp[m*1024+n].
__global__ __launch_bounds__(256) void hmma_gemm(
    const __nv_bfloat16* __restrict__ A2, const __nv_bfloat16* __restrict__ B2,
    const float* __restrict__ bias, float* __restrict__ outp, int mode)
{
    extern __shared__ __nv_bfloat16 sm2[];
    // sA: 2 stages x 128x64 (16KB each); sB likewise after 16384 elems
    const uint32_t sAu = smem_u32(sm2);
    const uint32_t sBu = sAu + 32768;

    const int tid = threadIdx.x;
    const int lane = tid & 31, wid = tid >> 5;
    const int m0 = blockIdx.x * 128, n0 = blockIdx.y * 128;

    // loader mapping: thread -> row r (0..127), 4 chunks of 16B starting at cb
    const int r = tid >> 1;
    const int cb = (tid & 1) * 4;
    const __nv_bfloat16* gA = A2 + (size_t)(m0 + r) * K3;
    const __nv_bfloat16* gB = B2 + (size_t)(n0 + r) * K3;
    uint32_t soff[4];
    #pragma unroll
    for (int j = 0; j < 4; j++)
        soff[j] = (uint32_t)(r * 128 + (((cb + j) ^ (r & 7)) << 4));

    const int wm = (wid & 1) * 64;
    const int wn = (wid >> 1) * 32;

    float c[4][4][4];
    #pragma unroll
    for (int a = 0; a < 4; a++)
        #pragma unroll
        for (int b = 0; b < 4; b++)
            #pragma unroll
            for (int d = 0; d < 4; d++) c[a][b][d] = 0.f;

    // prologue: stage 0
    {
        #pragma unroll
        for (int j = 0; j < 4; j++) cp16(sAu + soff[j], gA + (cb + j) * 8);
        #pragma unroll
        for (int j = 0; j < 4; j++) cp16(sBu + soff[j], gB + (cb + j) * 8);
        CP_COMMIT();
    }

    for (int kt = 0; kt < KITER; kt++) {
        const int st = kt & 1;
        if (kt + 1 < KITER) {
            const int k0 = (kt + 1) * 64;
            const uint32_t ao = sAu + (st ^ 1) * 16384;
            const uint32_t bo2 = sBu + (st ^ 1) * 16384;
            #pragma unroll
            for (int j = 0; j < 4; j++) cp16(ao + soff[j], gA + k0 + (cb + j) * 8);
            #pragma unroll
            for (int j = 0; j < 4; j++) cp16(bo2 + soff[j], gB + k0 + (cb + j) * 8);
            CP_COMMIT();
            asm volatile("cp.async.wait_group 1;" ::: "memory");
        } else {
            asm volatile("cp.async.wait_group 0;" ::: "memory");
        }
        __syncthreads();

        const uint32_t baseA = sAu + st * 16384;
        const uint32_t baseB = sBu + st * 16384;
        #pragma unroll
        for (int ks = 0; ks < 4; ks++) {
            const int kk = ks * 16;
            uint32_t a[4][4];
            #pragma unroll
            for (int mt = 0; mt < 4; mt++) {
                const int row = wm + mt * 16 + (lane & 15);
                const int kel = kk + ((lane >> 4) << 3);
                const uint32_t ad = baseA + (uint32_t)(row * 128 + ((((kel >> 3) & 7) ^ (row & 7)) << 4));
                ldmx4(a[mt], ad);
            }
            uint32_t b[2][4];
            #pragma unroll
            for (int bt = 0; bt < 2; bt++) {
                const int nrow = wn + bt * 16 + ((lane & 7) + ((lane >> 4) << 3));
                const int kel = kk + (((lane >> 3) & 1) << 3);
                const uint32_t bd = baseB + (uint32_t)(nrow * 128 + ((((kel >> 3) & 7) ^ (nrow & 7)) << 4));
                ldmx4(b[bt], bd);
            }
            #pragma unroll
            for (int mt = 0; mt < 4; mt++)
                #pragma unroll
                for (int nt = 0; nt < 4; nt++)
                    mma16816(c[mt][nt], a[mt], b[nt >> 1] + 2 * (nt & 1));
        }
        __syncthreads();
    }

    // epilogue
    const int mrow = m0 + wm + (lane >> 2);
    const int ncol = n0 + wn + (lane & 3) * 2;
    #pragma unroll
    for (int mt = 0; mt < 4; mt++) {
        #pragma unroll
        for (int nt = 0; nt < 4; nt++) {
            const int nn = ncol + nt * 8;
            const float bx = bias[nn], by = bias[nn + 1];
            #pragma unroll
            for (int half = 0; half < 2; half++) {
                const int mm = mrow + mt * 16 + half * 8;
                float2 o;
                o.x = c[mt][nt][half * 2 + 0] + bx;
                o.y = c[mt][nt][half * 2 + 1] + by;
                if (mode == 0) {
                    const int which = nn >> 10, h = (nn >> 6) & 15, d = nn & 63;
                    float* ob = (which == 0) ? g_Q : (which == 1) ? g_K : g_V;
                    const int bb = mm >> 11, s = mm & 2047;
                    *(float2*)(ob + (((size_t)(bb * SH + h)) * SS + s) * SD + d) = o;
                } else {
                    *(float2*)(outp + (size_t)mm * SDM + nn) = o;
                }
            }
        }
    }
}

// ---------------------------------------------------------------------------
// flash attention, fp32 (unchanged — passing at ~1040us)
// ---------------------------------------------------------------------------
__global__ __launch_bounds__(256) void attn_kernel()
{
    extern __shared__ float sm[];
    float* sQT = sm;
    float* sKT = sQT + 64 * 68;
    float* sV  = sKT + 64 * 68;
    float* sP  = sV + 64 * 64;

    const int bh = blockIdx.y;
    const int q0 = blockIdx.x * 64;
    const float* Qp = g_Q + (size_t)bh * SS * SD;
    const float* Kp = g_K + (size_t)bh * SS * SD;
    const float* Vp = g_V + (size_t)bh * SS * SD;

    const int tid = threadIdx.x;
    const int tx  = tid & 15, ty = tid >> 4;
    const int ty4 = ty * 4, tx4 = tx * 4;

    for (int i = tid; i < 1024; i += 256) {
        const int q = i >> 4, d4 = (i & 15) << 2;
        float4 v = *(const float4*)(Qp + (q0 + q) * SD + d4);
        sQT[(d4 + 0) * 68 + q] = v.x * 0.125f;
        sQT[(d4 + 1) * 68 + q] = v.y * 0.125f;
        sQT[(d4 + 2) * 68 + q] = v.z * 0.125f;
        sQT[(d4 + 3) * 68 + q] = v.w * 0.125f;
    }

    float m_i[4], l_i[4], acc[4][4];
    #pragma unroll
    for (int i = 0; i < 4; i++) {
        m_i[i] = -1e30f; l_i[i] = 0.f;
        #pragma unroll
        for (int j = 0; j < 4; j++) acc[i][j] = 0.f;
    }

    for (int t0 = 0; t0 < SS; t0 += 64) {
        __syncthreads();
        for (int i = tid; i < 1024; i += 256) {
            const int t = i >> 4, d4 = (i & 15) << 2;
            float4 kv = *(const float4*)(Kp + (t0 + t) * SD + d4);
            sKT[(d4 + 0) * 68 + t] = kv.x;
            sKT[(d4 + 1) * 68 + t] = kv.y;
            sKT[(d4 + 2) * 68 + t] = kv.z;
            sKT[(d4 + 3) * 68 + t] = kv.w;
            *(float4*)(sV + t * SD + d4) = *(const float4*)(Vp + (t0 + t) * SD + d4);
        }
        __syncthreads();

        float sc[4][4];
        #pragma unroll
        for (int i = 0; i < 4; i++)
            #pragma unroll
            for (int j = 0; j < 4; j++) sc[i][j] = 0.f;

        #pragma unroll
        for (int d = 0; d < 64; d += 4) {
            float a[4][4], bb[4][4];
            #pragma unroll
            for (int r2 = 0; r2 < 4; r2++) {
                float4 a4 = *(const float4*)(sQT + (d + r2) * 68 + ty4);
                a[r2][0] = a4.x; a[r2][1] = a4.y; a[r2][2] = a4.z; a[r2][3] = a4.w;
                float4 b4 = *(const float4*)(sKT + (d + r2) * 68 + tx4);
                bb[r2][0] = b4.x; bb[r2][1] = b4.y; bb[r2][2] = b4.z; bb[r2][3] = b4.w;
            }
            #pragma unroll
            for (int r2 = 0; r2 < 4; r2++)
                #pragma unroll
                for (int i = 0; i < 4; i++)
                    #pragma unroll
                    for (int j = 0; j < 4; j++) sc[i][j] += a[r2][i] * bb[r2][j];
        }

        #pragma unroll
        for (int i = 0; i < 4; i++) {
            float mx = fmaxf(fmaxf(sc[i][0], sc[i][1]), fmaxf(sc[i][2], sc[i][3]));
            #pragma unroll
            for (int off = 8; off; off >>= 1)
                mx = fmaxf(mx, __shfl_xor_sync(0xffffffffu, mx, off, 16));
            const float mn   = fmaxf(m_i[i], mx);
            const float corr = __expf(m_i[i] - mn);
            m_i[i] = mn;
            float rs = 0.f;
            #pragma unroll
            for (int j = 0; j < 4; j++) { sc[i][j] = __expf(sc[i][j] - mn); rs += sc[i][j]; }
            #pragma unroll
            for (int off = 8; off; off >>= 1)
                rs += __shfl_xor_sync(0xffffffffu, rs, off, 16);
            l_i[i] = l_i[i] * corr + rs;
            #pragma unroll
            for (int j = 0; j < 4; j++) acc[i][j] *= corr;
            float4 p4; p4.x = sc[i][0]; p4.y = sc[i][1]; p4.z = sc[i][2]; p4.w = sc[i][3];
            *(float4*)(sP + (ty4 + i) * SD + tx4) = p4;
        }
        __syncthreads();

        #pragma unroll
        for (int k = 0; k < 64; k += 4) {
            float p[4][4], v[4][4];
            #pragma unroll
            for (int i = 0; i < 4; i++) {
                float4 p4 = *(const float4*)(sP + (ty4 + i) * SD + k);
                p[i][0] = p4.x; p[i][1] = p4.y; p[i][2] = p4.z; p[i][3] = p4.w;
            }
            #pragma unroll
            for (int r2 = 0; r2 < 4; r2++) {
                float4 v4 = *(const float4*)(sV + (k + r2) * SD + tx4);
                v[r2][0] = v4.x; v[r2][1] = v4.y; v[r2][2] = v4.z; v[r2][3] = v4.w;
            }
            #pragma unroll
            for (int i = 0; i < 4; i++)
                #pragma unroll
                for (int j = 0; j < 4; j++)
                    acc[i][j] += p[i][0] * v[0][j] + p[i][1] * v[1][j]
                               + p[i][2] * v[2][j] + p[i][3] * v[3][j];
        }
    }

    const int bb2 = bh >> 4, h = bh & 15;
    #pragma unroll
    for (int i = 0; i < 4; i++) {
        const float inv = 1.f / l_i[i];
        const int s = q0 + ty4 + i;
        float4 o;
        o.x = acc[i][0] * inv; o.y = acc[i][1] * inv;
        o.z = acc[i][2] * inv; o.w = acc[i][3] * inv;
        *(float4*)(g_A + (((size_t)bb2 * SS + s) * SH + h) * SD + tx4) = o;
    }
}

// ---------------------------------------------------------------------------
extern "C" void kernel_launch(void* const* d_in, const int* in_sizes, int n_in,
                              void* d_out, int out_size)
{
    const float* x  = (const float*)d_in[0];
    const float* Wq = (const float*)d_in[1];
    const float* bq = (const float*)d_in[2];
    const float* Wk = (const float*)d_in[3];
    const float* bk = (const float*)d_in[4];
    const float* Wv = (const float*)d_in[5];
    const float* bv = (const float*)d_in[6];
    const float* Wo = (const float*)d_in[7];
    const float* bo = (const float*)d_in[8];
    float* out = (float*)d_out;

    __nv_bfloat16 *x2, *a2, *b2q, *b2o;
    float *biasq, *gA;
    cudaGetSymbolAddress((void**)&x2, g_X2);
    cudaGetSymbolAddress((void**)&a2, g_A2);
    cudaGetSymbolAddress((void**)&b2q, g_B2qkv);
    cudaGetSymbolAddress((void**)&b2o, g_B2o);
    cudaGetSymbolAddress((void**)&biasq, g_bias_qkv);
    cudaGetSymbolAddress((void**)&gA, g_A);

    conv_split2<<<512, 256>>>(x, x2);
    conv_wqkv2<<<512, 256>>>(Wq, bq, Wk, bk, Wv, bv);
    conv_wo2<<<256, 256>>>(Wo);

    const int gemm_smem = 65536;
    cudaFuncSetAttribute(hmma_gemm, cudaFuncAttributeMaxDynamicSharedMemorySize, gemm_smem);

    // QKV fused: [4096 x 3072 x 3072]
    hmma_gemm<<<dim3(MTOT / 128, NQKV / 128), 256, gemm_smem>>>(x2, b2q, biasq, nullptr, 0);

    // attention (fp32)
    const int attn_smem = (2 * 64 * 68 + 2 * 64 * 64) * (int)sizeof(float);
    cudaFuncSetAttribute(attn_kernel, cudaFuncAttributeMaxDynamicSharedMemorySize, attn_smem);
    attn_kernel<<<dim3(SS / 64, SB * SH), 256, attn_smem>>>();

    // proj: [4096 x 1024 x 3072]
    conv_split2<<<512, 256>>>(gA, a2);
    hmma_gemm<<<dim3(MTOT / 128, SDM / 128), 256, gemm_smem>>>(a2, b2o, bo, out, 1);
}

// round 4
// speedup vs baseline: 2.4654x; 1.8854x over previous
#include <cuda_runtime.h>
#include <cuda_bf16.h>
#include <cstdint>

#define SB   2
#define SS   2048
#define SH   16
#define SD   64
#define SDM  1024
#define MTOT (SB * SS)   // 4096
#define NQKV 3072
#define K3   3072        // concatenated split-K
#define KITER 48         // K3 / 64
#define QSCALE 0.18033688f   // 0.125 * log2(e)

// ------------------------- device scratch (no allocs) -----------------------
__device__ __nv_bfloat16 g_Qhi[SB * SH * SS * SD];  // [B,H,S,D], pre-scaled
__device__ __nv_bfloat16 g_Qlo[SB * SH * SS * SD];
__device__ __nv_bfloat16 g_Khi[SB * SH * SS * SD];
__device__ __nv_bfloat16 g_Klo[SB * SH * SS * SD];
__device__ __nv_bfloat16 g_Vthi[SB * SH * SD * SS]; // [B,H,D,S] transposed
__device__ __nv_bfloat16 g_Vtlo[SB * SH * SD * SS];

__device__ __nv_bfloat16 g_X2[MTOT * K3];     // [m][k']: hi|hi|lo
__device__ __nv_bfloat16 g_A2[MTOT * K3];     // [m][k']: hi|hi|lo (attn out)
__device__ __nv_bfloat16 g_B2qkv[NQKV * K3];  // [n][k']: hi|lo|hi
__device__ __nv_bfloat16 g_B2o[SDM * K3];     // [n][k']: hi|lo|hi
__device__ float g_bias_qkv[NQKV];

// ------------------------------ PTX helpers ---------------------------------
__device__ __forceinline__ uint32_t smem_u32(const void* p) {
    uint32_t a;
    asm("{ .reg .u64 t; cvta.to.shared.u64 t, %1; cvt.u32.u64 %0, t; }" : "=r"(a) : "l"(p));
    return a;
}
__device__ __forceinline__ void cp16(uint32_t dst, const void* src) {
    asm volatile("cp.async.cg.shared.global [%0], [%1], 16;" :: "r"(dst), "l"(src));
}
#define CP_COMMIT() asm volatile("cp.async.commit_group;" ::: "memory")

__device__ __forceinline__ void ldmx4(uint32_t* r, uint32_t addr) {
    asm volatile("ldmatrix.sync.aligned.m8n8.x4.shared.b16 {%0,%1,%2,%3}, [%4];"
        : "=r"(r[0]), "=r"(r[1]), "=r"(r[2]), "=r"(r[3]) : "r"(addr));
}
__device__ __forceinline__ void mma16816(float* c, const uint32_t* a, const uint32_t* b) {
    asm volatile(
        "mma.sync.aligned.m16n8k16.row.col.f32.bf16.bf16.f32 "
        "{%0,%1,%2,%3}, {%4,%5,%6,%7}, {%8,%9}, {%0,%1,%2,%3};"
        : "+f"(c[0]), "+f"(c[1]), "+f"(c[2]), "+f"(c[3])
        : "r"(a[0]), "r"(a[1]), "r"(a[2]), "r"(a[3]), "r"(b[0]), "r"(b[1]));
}
__device__ __forceinline__ float ex2(float x) {
    float y; asm("ex2.approx.ftz.f32 %0, %1;" : "=f"(y) : "f"(x)); return y;
}
__device__ __forceinline__ void split2(float v, __nv_bfloat16& h, __nv_bfloat16& l) {
    h = __float2bfloat16(v);
    l = __float2bfloat16(v - __bfloat162float(h));
}
__device__ __forceinline__ uint32_t pack2(__nv_bfloat16 a, __nv_bfloat16 b) {
    __nv_bfloat162 t(a, b); return *reinterpret_cast<uint32_t*>(&t);
}

// ----------------------------- conversion kernels ---------------------------
__global__ void conv_split2(const float* __restrict__ src, __nv_bfloat16* __restrict__ dst)
{
    const int n = MTOT * SDM;
    for (int i = blockIdx.x * blockDim.x + threadIdx.x; i < n; i += gridDim.x * blockDim.x) {
        const int m = i >> 10, k = i & 1023;
        float v = src[i];
        __nv_bfloat16 hi, lo; split2(v, hi, lo);
        const size_t base = (size_t)m * K3;
        dst[base + k] = hi;
        dst[base + 1024 + k] = hi;
        dst[base + 2048 + k] = lo;
    }
}

__global__ void conv_wqkv2(const float* __restrict__ Wq, const float* __restrict__ bq,
                           const float* __restrict__ Wk, const float* __restrict__ bk,
                           const float* __restrict__ Wv, const float* __restrict__ bv)
{
    const int n_el = NQKV * SDM;
    for (int i = blockIdx.x * blockDim.x + threadIdx.x; i < n_el; i += gridDim.x * blockDim.x) {
        const int n = i >> 10, k = i & 1023;
        const int which = n >> 10, h = (n >> 6) & 15, d = n & 63;
        const float* W = (which == 0) ? Wq : (which == 1) ? Wk : Wv;
        float v = W[((size_t)h * SDM + k) * SD + d];
        __nv_bfloat16 hi, lo; split2(v, hi, lo);
        const size_t base = (size_t)n * K3;
        g_B2qkv[base + k] = hi;
        g_B2qkv[base + 1024 + k] = lo;
        g_B2qkv[base + 2048 + k] = hi;
        if (k == 0) {
            const float* bb = (which == 0) ? bq : (which == 1) ? bk : bv;
            g_bias_qkv[n] = bb[h * SD + d];
        }
    }
}

__global__ void conv_wo2(const float* __restrict__ Wo)
{
    const int n_el = SDM * SDM;
    for (int i = blockIdx.x * blockDim.x + threadIdx.x; i < n_el; i += gridDim.x * blockDim.x) {
        const int n = i >> 10, k = i & 1023;
        float v = Wo[(size_t)k * SDM + n];
        __nv_bfloat16 hi, lo; split2(v, hi, lo);
        const size_t base = (size_t)n * K3;
        g_B2o[base + k] = hi;
        g_B2o[base + 1024 + k] = lo;
        g_B2o[base + 2048 + k] = hi;
    }
}

// ------------------------- bf16 mma.sync GEMM -------------------------------
// C[M, N] = A2[M, K3] * B2[N, K3]^T (+ bias[n])
// mode 0: split-write Q/K (bf16 hi/lo, Q pre-scaled) and V transposed.
// mode 1: outp[m*1024+n] fp32.
__global__ __launch_bounds__(256) void hmma_gemm(
    const __nv_bfloat16* __restrict__ A2, const __nv_bfloat16* __restrict__ B2,
    const float* __restrict__ bias, float* __restrict__ outp, int mode)
{
    extern __shared__ __nv_bfloat16 sm2[];
    const uint32_t sAu = smem_u32(sm2);
    const uint32_t sBu = sAu + 32768;

    const int tid = threadIdx.x;
    const int lane = tid & 31, wid = tid >> 5;
    const int m0 = blockIdx.x * 128, n0 = blockIdx.y * 128;

    const int r = tid >> 1;
    const int cb = (tid & 1) * 4;
    const __nv_bfloat16* gA = A2 + (size_t)(m0 + r) * K3;
    const __nv_bfloat16* gB = B2 + (size_t)(n0 + r) * K3;
    uint32_t soff[4];
    #pragma unroll
    for (int j = 0; j < 4; j++)
        soff[j] = (uint32_t)(r * 128 + (((cb + j) ^ (r & 7)) << 4));

    const int wm = (wid & 1) * 64;
    const int wn = (wid >> 1) * 32;

    float c[4][4][4];
    #pragma unroll
    for (int a = 0; a < 4; a++)
        #pragma unroll
        for (int b = 0; b < 4; b++)
            #pragma unroll
            for (int d = 0; d < 4; d++) c[a][b][d] = 0.f;

    {
        #pragma unroll
        for (int j = 0; j < 4; j++) cp16(sAu + soff[j], gA + (cb + j) * 8);
        #pragma unroll
        for (int j = 0; j < 4; j++) cp16(sBu + soff[j], gB + (cb + j) * 8);
        CP_COMMIT();
    }

    for (int kt = 0; kt < KITER; kt++) {
        const int st = kt & 1;
        if (kt + 1 < KITER) {
            const int k0 = (kt + 1) * 64;
            const uint32_t ao = sAu + (st ^ 1) * 16384;
            const uint32_t bo2 = sBu + (st ^ 1) * 16384;
            #pragma unroll
            for (int j = 0; j < 4; j++) cp16(ao + soff[j], gA + k0 + (cb + j) * 8);
            #pragma unroll
            for (int j = 0; j < 4; j++) cp16(bo2 + soff[j], gB + k0 + (cb + j) * 8);
            CP_COMMIT();
            asm volatile("cp.async.wait_group 1;" ::: "memory");
        } else {
            asm volatile("cp.async.wait_group 0;" ::: "memory");
        }
        __syncthreads();

        const uint32_t baseA = sAu + st * 16384;
        const uint32_t baseB = sBu + st * 16384;
        #pragma unroll
        for (int ks = 0; ks < 4; ks++) {
            const int kk = ks * 16;
            uint32_t a[4][4];
            #pragma unroll
            for (int mt = 0; mt < 4; mt++) {
                const int row = wm + mt * 16 + (lane & 15);
                const int kel = kk + ((lane >> 4) << 3);
                const uint32_t ad = baseA + (uint32_t)(row * 128 + ((((kel >> 3) & 7) ^ (row & 7)) << 4));
                ldmx4(a[mt], ad);
            }
            uint32_t b[2][4];
            #pragma unroll
            for (int bt = 0; bt < 2; bt++) {
                const int nrow = wn + bt * 16 + ((lane & 7) + ((lane >> 4) << 3));
                const int kel = kk + (((lane >> 3) & 1) << 3);
                const uint32_t bd = baseB + (uint32_t)(nrow * 128 + ((((kel >> 3) & 7) ^ (nrow & 7)) << 4));
                ldmx4(b[bt], bd);
            }
            #pragma unroll
            for (int mt = 0; mt < 4; mt++)
                #pragma unroll
                for (int nt = 0; nt < 4; nt++)
                    mma16816(c[mt][nt], a[mt], b[nt >> 1] + 2 * (nt & 1));
        }
        __syncthreads();
    }

    // epilogue
    const int mrow = m0 + wm + (lane >> 2);
    const int ncol = n0 + wn + (lane & 3) * 2;
    #pragma unroll
    for (int mt = 0; mt < 4; mt++) {
        #pragma unroll
        for (int nt = 0; nt < 4; nt++) {
            const int nn = ncol + nt * 8;
            const float bx = bias[nn], by = bias[nn + 1];
            #pragma unroll
            for (int half = 0; half < 2; half++) {
                const int mm = mrow + mt * 16 + half * 8;
                float vx = c[mt][nt][half * 2 + 0] + bx;
                float vy = c[mt][nt][half * 2 + 1] + by;
                if (mode == 1) {
                    float2 o; o.x = vx; o.y = vy;
                    *(float2*)(outp + (size_t)mm * SDM + nn) = o;
                } else {
                    const int which = nn >> 10, h = (nn >> 6) & 15, d = nn & 63;
                    const int b = mm >> 11, s = mm & 2047;
                    const int bh = b * SH + h;
                    if (which == 0) { vx *= QSCALE; vy *= QSCALE; }
                    __nv_bfloat16 hx, lx, hy, ly;
                    split2(vx, hx, lx); split2(vy, hy, ly);
                    if (which == 2) {
                        const size_t i0 = ((size_t)bh * SD + d) * SS + s;
                        g_Vthi[i0] = hx; g_Vtlo[i0] = lx;
                        g_Vthi[i0 + SS] = hy; g_Vtlo[i0 + SS] = ly;
                    } else {
                        const size_t idx = ((size_t)bh * SS + s) * SD + d;
                        __nv_bfloat16* ph = (which == 0) ? g_Qhi : g_Khi;
                        __nv_bfloat16* pl = (which == 0) ? g_Qlo : g_Klo;
                        *(__nv_bfloat162*)(ph + idx) = __nv_bfloat162(hx, hy);
                        *(__nv_bfloat162*)(pl + idx) = __nv_bfloat162(lx, ly);
                    }
                }
            }
        }
    }
}

// ---------------------------------------------------------------------------
// tensor-core flash attention
// grid (16, 32): q-tile 128 x (b,h). 8 warps x 16 q-rows. K/V tile 64, 2 stages.
// smem: Qhi/Qlo 16KB each + 2 stages x [Kh|Kl|Vh|Vl] 8KB each = 96KB
// ---------------------------------------------------------------------------
__global__ __launch_bounds__(256, 2) void attn_mma()
{
    extern __shared__ __nv_bfloat16 smA[];
    const uint32_t sQh = smem_u32(smA);
    const uint32_t sQl = sQh + 16384;
    const uint32_t sT  = sQl + 16384;   // stage st at sT + st*32768

    const int tid = threadIdx.x, lane = tid & 31, wid = tid >> 5;
    const int bh = blockIdx.y, q0 = blockIdx.x * 128;
    const __nv_bfloat16* Qh = g_Qhi + (size_t)bh * SS * SD;
    const __nv_bfloat16* Ql = g_Qlo + (size_t)bh * SS * SD;
    const __nv_bfloat16* Kh = g_Khi + (size_t)bh * SS * SD;
    const __nv_bfloat16* Kl = g_Klo + (size_t)bh * SS * SD;
    const __nv_bfloat16* Vh = g_Vthi + (size_t)bh * SD * SS;
    const __nv_bfloat16* Vl = g_Vtlo + (size_t)bh * SD * SS;

    // load Q tiles (once)
    {
        const int rq = tid >> 1, cb = (tid & 1) * 4;
        const __nv_bfloat16* ph = Qh + (size_t)(q0 + rq) * SD;
        const __nv_bfloat16* pl = Ql + (size_t)(q0 + rq) * SD;
        #pragma unroll
        for (int j = 0; j < 4; j++) {
            const uint32_t off = (uint32_t)(rq * 128 + (((cb + j) ^ (rq & 7)) << 4));
            cp16(sQh + off, ph + (cb + j) * 8);
            cp16(sQl + off, pl + (cb + j) * 8);
        }
    }

    const int r2 = tid >> 2, cb2 = (tid & 3) * 2;
    uint32_t toff[2];
    #pragma unroll
    for (int j = 0; j < 2; j++)
        toff[j] = (uint32_t)(r2 * 128 + (((cb2 + j) ^ (r2 & 7)) << 4));
    const __nv_bfloat16* pKh = Kh + (size_t)r2 * SD;
    const __nv_bfloat16* pKl = Kl + (size_t)r2 * SD;
    const __nv_bfloat16* pVh = Vh + (size_t)r2 * SS;
    const __nv_bfloat16* pVl = Vl + (size_t)r2 * SS;

    auto load_tile = [&](int itile, int st) {
        const uint32_t b0 = sT + st * 32768;
        const int t0 = itile * 64;
        #pragma unroll
        for (int j = 0; j < 2; j++) {
            cp16(b0 +         toff[j], pKh + (size_t)t0 * SD + (cb2 + j) * 8);
            cp16(b0 + 8192 +  toff[j], pKl + (size_t)t0 * SD + (cb2 + j) * 8);
            cp16(b0 + 16384 + toff[j], pVh + t0 + (cb2 + j) * 8);
            cp16(b0 + 24576 + toff[j], pVl + t0 + (cb2 + j) * 8);
        }
    };
    load_tile(0, 0);
    CP_COMMIT();

    float m0 = -1e30f, m1 = -1e30f, l0 = 0.f, l1 = 0.f;
    float o[8][4];
    #pragma unroll
    for (int f = 0; f < 8; f++)
        #pragma unroll
        for (int d = 0; d < 4; d++) o[f][d] = 0.f;

    for (int it = 0; it < 32; it++) {
        const int st = it & 1;
        if (it + 1 < 32) {
            load_tile(it + 1, st ^ 1);
            CP_COMMIT();
            asm volatile("cp.async.wait_group 1;" ::: "memory");
        } else {
            asm volatile("cp.async.wait_group 0;" ::: "memory");
        }
        __syncthreads();

        const uint32_t bKh = sT + st * 32768, bKl = bKh + 8192;
        const uint32_t bVh = bKh + 16384,    bVl = bKh + 24576;

        // scores (log2 domain; Q pre-scaled)
        float c[8][4];
        #pragma unroll
        for (int f = 0; f < 8; f++)
            #pragma unroll
            for (int d = 0; d < 4; d++) c[f][d] = 0.f;

        #pragma unroll
        for (int ks = 0; ks < 4; ks++) {
            const int kk = ks * 16;
            uint32_t aQh[4], aQl[4];
            {
                const int row = wid * 16 + (lane & 15);
                const int kel = kk + ((lane >> 4) << 3);
                const uint32_t ao = (uint32_t)(row * 128 + ((((kel >> 3) & 7) ^ (row & 7)) << 4));
                ldmx4(aQh, sQh + ao);
                ldmx4(aQl, sQl + ao);
            }
            #pragma unroll
            for (int bt = 0; bt < 4; bt++) {
                const int nrow = bt * 16 + (lane & 7) + ((lane >> 4) << 3);
                const int kel = kk + (((lane >> 3) & 1) << 3);
                const uint32_t bo = (uint32_t)(nrow * 128 + ((((kel >> 3) & 7) ^ (nrow & 7)) << 4));
                uint32_t bKf[4], bLf[4];
                ldmx4(bKf, bKh + bo);
                ldmx4(bLf, bKl + bo);
                #pragma unroll
                for (int h2 = 0; h2 < 2; h2++) {
                    mma16816(c[bt * 2 + h2], aQh, bKf + 2 * h2);
                    mma16816(c[bt * 2 + h2], aQh, bLf + 2 * h2);
                    mma16816(c[bt * 2 + h2], aQl, bKf + 2 * h2);
                }
            }
        }

        // online softmax (rows r=lane>>2 and r+8; reduce over quad)
        float mx0 = -1e30f, mx1 = -1e30f;
        #pragma unroll
        for (int f = 0; f < 8; f++) {
            mx0 = fmaxf(mx0, fmaxf(c[f][0], c[f][1]));
            mx1 = fmaxf(mx1, fmaxf(c[f][2], c[f][3]));
        }
        mx0 = fmaxf(mx0, __shfl_xor_sync(0xffffffffu, mx0, 1));
        mx0 = fmaxf(mx0, __shfl_xor_sync(0xffffffffu, mx0, 2));
        mx1 = fmaxf(mx1, __shfl_xor_sync(0xffffffffu, mx1, 1));
        mx1 = fmaxf(mx1, __shfl_xor_sync(0xffffffffu, mx1, 2));
        const float mn0 = fmaxf(m0, mx0), mn1 = fmaxf(m1, mx1);
        const float corr0 = ex2(m0 - mn0), corr1 = ex2(m1 - mn1);
        m0 = mn0; m1 = mn1;

        uint32_t pA0[8], pA1[8], pL0[8], pL1[8];
        float rs0 = 0.f, rs1 = 0.f;
        #pragma unroll
        for (int f = 0; f < 8; f++) {
            const float p0 = ex2(c[f][0] - mn0), p1 = ex2(c[f][1] - mn0);
            const float p2 = ex2(c[f][2] - mn1), p3 = ex2(c[f][3] - mn1);
            rs0 += p0 + p1; rs1 += p2 + p3;
            __nv_bfloat16 h0, l0b, h1, l1b, h2b, l2b, h3, l3b;
            split2(p0, h0, l0b); split2(p1, h1, l1b);
            split2(p2, h2b, l2b); split2(p3, h3, l3b);
            pA0[f] = pack2(h0, h1);  pA1[f] = pack2(h2b, h3);
            pL0[f] = pack2(l0b, l1b); pL1[f] = pack2(l2b, l3b);
        }
        rs0 += __shfl_xor_sync(0xffffffffu, rs0, 1);
        rs0 += __shfl_xor_sync(0xffffffffu, rs0, 2);
        rs1 += __shfl_xor_sync(0xffffffffu, rs1, 1);
        rs1 += __shfl_xor_sync(0xffffffffu, rs1, 2);
        l0 = l0 * corr0 + rs0;
        l1 = l1 * corr1 + rs1;
        #pragma unroll
        for (int f = 0; f < 8; f++) {
            o[f][0] *= corr0; o[f][1] *= corr0;
            o[f][2] *= corr1; o[f][3] *= corr1;
        }

        // O += P . V  (P frags from registers, V^T frags from smem)
        #pragma unroll
        for (int tc = 0; tc < 4; tc++) {
            uint32_t aPh[4] = {pA0[2 * tc], pA1[2 * tc], pA0[2 * tc + 1], pA1[2 * tc + 1]};
            uint32_t aPl[4] = {pL0[2 * tc], pL1[2 * tc], pL0[2 * tc + 1], pL1[2 * tc + 1]};
            #pragma unroll
            for (int bt = 0; bt < 4; bt++) {
                const int nrow = bt * 16 + (lane & 7) + ((lane >> 4) << 3);
                const int kel = tc * 16 + (((lane >> 3) & 1) << 3);
                const uint32_t bo = (uint32_t)(nrow * 128 + ((((kel >> 3) & 7) ^ (nrow & 7)) << 4));
                uint32_t bVf[4], bWf[4];
                ldmx4(bVf, bVh + bo);
                ldmx4(bWf, bVl + bo);
                #pragma unroll
                for (int h2 = 0; h2 < 2; h2++) {
                    mma16816(o[bt * 2 + h2], aPh, bVf + 2 * h2);
                    mma16816(o[bt * 2 + h2], aPh, bWf + 2 * h2);
                    mma16816(o[bt * 2 + h2], aPl, bVf + 2 * h2);
                }
            }
        }
        __syncthreads();
    }

    // epilogue: write A2 (hi|hi|lo) for the proj GEMM
    const float inv0 = 1.f / l0, inv1 = 1.f / l1;
    const int b = bh >> 4, h = bh & 15;
    const int rr = lane >> 2, cc = (lane & 3) * 2;
    const int s0 = q0 + wid * 16 + rr;
    const size_t mrow0 = ((size_t)b * SS + s0) * K3;
    const size_t mrow1 = mrow0 + (size_t)8 * K3;
    #pragma unroll
    for (int f = 0; f < 8; f++) {
        const int kb = h * 64 + f * 8 + cc;
        {
            const float v0 = o[f][0] * inv0, v1 = o[f][1] * inv0;
            __nv_bfloat16 h0, l0b, h1, l1b;
            split2(v0, h0, l0b); split2(v1, h1, l1b);
            *(__nv_bfloat162*)(g_A2 + mrow0 + kb)        = __nv_bfloat162(h0, h1);
            *(__nv_bfloat162*)(g_A2 + mrow0 + 1024 + kb) = __nv_bfloat162(h0, h1);
            *(__nv_bfloat162*)(g_A2 + mrow0 + 2048 + kb) = __nv_bfloat162(l0b, l1b);
        }
        {
            const float v0 = o[f][2] * inv1, v1 = o[f][3] * inv1;
            __nv_bfloat16 h0, l0b, h1, l1b;
            split2(v0, h0, l0b); split2(v1, h1, l1b);
            *(__nv_bfloat162*)(g_A2 + mrow1 + kb)        = __nv_bfloat162(h0, h1);
            *(__nv_bfloat162*)(g_A2 + mrow1 + 1024 + kb) = __nv_bfloat162(h0, h1);
            *(__nv_bfloat162*)(g_A2 + mrow1 + 2048 + kb) = __nv_bfloat162(l0b, l1b);
        }
    }
}

// ---------------------------------------------------------------------------
extern "C" void kernel_launch(void* const* d_in, const int* in_sizes, int n_in,
                              void* d_out, int out_size)
{
    const float* x  = (const float*)d_in[0];
    const float* Wq = (const float*)d_in[1];
    const float* bq = (const float*)d_in[2];
    const float* Wk = (const float*)d_in[3];
    const float* bk = (const float*)d_in[4];
    const float* Wv = (const float*)d_in[5];
    const float* bv = (const float*)d_in[6];
    const float* Wo = (const float*)d_in[7];
    const float* bo = (const float*)d_in[8];
    float* out = (float*)d_out;

    __nv_bfloat16 *x2, *a2, *b2q, *b2o;
    float *biasq;
    cudaGetSymbolAddress((void**)&x2, g_X2);
    cudaGetSymbolAddress((void**)&a2, g_A2);
    cudaGetSymbolAddress((void**)&b2q, g_B2qkv);
    cudaGetSymbolAddress((void**)&b2o, g_B2o);
    cudaGetSymbolAddress((void**)&biasq, g_bias_qkv);

    conv_split2<<<512, 256>>>(x, x2);
    conv_wqkv2<<<512, 256>>>(Wq, bq, Wk, bk, Wv, bv);
    conv_wo2<<<256, 256>>>(Wo);

    const int gemm_smem = 65536;
    cudaFuncSetAttribute(hmma_gemm, cudaFuncAttributeMaxDynamicSharedMemorySize, gemm_smem);

    // QKV fused: [4096 x 3072 x 3072] -> Q/K/Vt bf16 splits
    hmma_gemm<<<dim3(MTOT / 128, NQKV / 128), 256, gemm_smem>>>(x2, b2q, biasq, nullptr, 0);

    // tensor-core attention -> g_A2
    const int attn_smem = 98304;
    cudaFuncSetAttribute(attn_mma, cudaFuncAttributeMaxDynamicSharedMemorySize, attn_smem);
    attn_mma<<<dim3(SS / 128, SB * SH), 256, attn_smem>>>();

    // proj: [4096 x 1024 x 3072]
    hmma_gemm<<<dim3(MTOT / 128, SDM / 128), 256, gemm_smem>>>(a2, b2o, bo, out, 1);
}

// round 6
// speedup vs baseline: 3.0090x; 1.2205x over previous
#include <cuda_runtime.h>
#include <cuda_bf16.h>
#include <cstdint>

#define SB   2
#define SS   2048
#define SH   16
#define SD   64
#define SDM  1024
#define MTOT (SB * SS)   // 4096
#define NQKV 3072
#define KITER 48         // 3 segments x 16 stages of BK=64
#define QSCALE 0.18033688f   // 0.125 * log2(e)

// ------------------------- device scratch (no allocs) -----------------------
__device__ __nv_bfloat16 g_Qhi[SB * SH * SS * SD];  // [B,H,S,D], pre-scaled
__device__ __nv_bfloat16 g_Qlo[SB * SH * SS * SD];
__device__ __nv_bfloat16 g_Khi[SB * SH * SS * SD];
__device__ __nv_bfloat16 g_Klo[SB * SH * SS * SD];
__device__ __nv_bfloat16 g_Vthi[SB * SH * SD * SS]; // [B,H,D,S] transposed
__device__ __nv_bfloat16 g_Vtlo[SB * SH * SD * SS];

__device__ __nv_bfloat16 g_Xhi[MTOT * SDM];
__device__ __nv_bfloat16 g_Xlo[MTOT * SDM];
__device__ __nv_bfloat16 g_Whi[NQKV * SDM];   // [n][k]
__device__ __nv_bfloat16 g_Wlo[NQKV * SDM];
__device__ __nv_bfloat16 g_Wohi[SDM * SDM];   // [n][k] = Wo[k][n]
__device__ __nv_bfloat16 g_Wolo[SDM * SDM];
__device__ __nv_bfloat16 g_AOhi[MTOT * SDM];  // attention out
__device__ __nv_bfloat16 g_AOlo[MTOT * SDM];
__device__ float g_bias_qkv[NQKV];

// ------------------------------ PTX helpers ---------------------------------
__device__ __forceinline__ uint32_t smem_u32(const void* p) {
    uint32_t a;
    asm("{ .reg .u64 t; cvta.to.shared.u64 t, %1; cvt.u32.u64 %0, t; }" : "=r"(a) : "l"(p));
    return a;
}
__device__ __forceinline__ void cp16(uint32_t dst, const void* src) {
    asm volatile("cp.async.cg.shared.global [%0], [%1], 16;" :: "r"(dst), "l"(src));
}
#define CP_COMMIT() asm volatile("cp.async.commit_group;" ::: "memory")

__device__ __forceinline__ void ldmx4(uint32_t* r, uint32_t addr) {
    asm volatile("ldmatrix.sync.aligned.m8n8.x4.shared.b16 {%0,%1,%2,%3}, [%4];"
        : "=r"(r[0]), "=r"(r[1]), "=r"(r[2]), "=r"(r[3]) : "r"(addr));
}
__device__ __forceinline__ void mma16816(float* c, const uint32_t* a, const uint32_t* b) {
    asm volatile(
        "mma.sync.aligned.m16n8k16.row.col.f32.bf16.bf16.f32 "
        "{%0,%1,%2,%3}, {%4,%5,%6,%7}, {%8,%9}, {%0,%1,%2,%3};"
        : "+f"(c[0]), "+f"(c[1]), "+f"(c[2]), "+f"(c[3])
        : "r"(a[0]), "r"(a[1]), "r"(a[2]), "r"(a[3]), "r"(b[0]), "r"(b[1]));
}
__device__ __forceinline__ float ex2(float x) {
    float y; asm("ex2.approx.ftz.f32 %0, %1;" : "=f"(y) : "f"(x)); return y;
}
__device__ __forceinline__ void split2(float v, __nv_bfloat16& h, __nv_bfloat16& l) {
    h = __float2bfloat16(v);
    l = __float2bfloat16(v - __bfloat162float(h));
}
__device__ __forceinline__ uint32_t pack2(__nv_bfloat16 a, __nv_bfloat16 b) {
    __nv_bfloat162 t(a, b); return *reinterpret_cast<uint32_t*>(&t);
}

// ----------------------------- conversion kernels ---------------------------
__global__ void conv_x(const float* __restrict__ src,
                       __nv_bfloat16* __restrict__ hi, __nv_bfloat16* __restrict__ lo,
                       int n)
{
    for (int i = blockIdx.x * blockDim.x + threadIdx.x; i < n; i += gridDim.x * blockDim.x) {
        __nv_bfloat16 h, l; split2(src[i], h, l);
        hi[i] = h; lo[i] = l;
    }
}

__global__ void conv_wqkv(const float* __restrict__ Wq, const float* __restrict__ bq,
                          const float* __restrict__ Wk, const float* __restrict__ bk,
                          const float* __restrict__ Wv, const float* __restrict__ bv)
{
    const int n_el = NQKV * SDM;
    for (int i = blockIdx.x * blockDim.x + threadIdx.x; i < n_el; i += gridDim.x * blockDim.x) {
        const int n = i >> 10, k = i & 1023;
        const int which = n >> 10, h = (n >> 6) & 15, d = n & 63;
        const float* W = (which == 0) ? Wq : (which == 1) ? Wk : Wv;
        float v = W[((size_t)h * SDM + k) * SD + d];
        __nv_bfloat16 hi, lo; split2(v, hi, lo);
        g_Whi[i] = hi; g_Wlo[i] = lo;
        if (k == 0) {
            const float* bb = (which == 0) ? bq : (which == 1) ? bk : bv;
            g_bias_qkv[n] = bb[h * SD + d];
        }
    }
}

__global__ void conv_wo(const float* __restrict__ Wo)
{
    const int n_el = SDM * SDM;
    for (int i = blockIdx.x * blockDim.x + threadIdx.x; i < n_el; i += gridDim.x * blockDim.x) {
        const int n = i >> 10, k = i & 1023;
        __nv_bfloat16 hi, lo; split2(Wo[(size_t)k * SDM + n], hi, lo);
        g_Wohi[i] = hi; g_Wolo[i] = lo;
    }
}

// ------------------------- bf16x3 mma.sync GEMM ------------------------------
// C[M,N] = A[M,1024] * B[N,1024]^T via 3 compensated segments (AhBh+AhBl+AlBh).
// CTA 128x128, 4 warps, warp tile 64x64, BK=64, 3-stage cp.async pipeline.
// mode 0: split-write Q/K (bf16 hi/lo, Q pre-scaled) and V transposed.
// mode 1: outp[m*1024+n] fp32 (+bias).
__global__ __launch_bounds__(128, 2) void hmma_gemm(
    const __nv_bfloat16* __restrict__ Ahi, const __nv_bfloat16* __restrict__ Alo,
    const __nv_bfloat16* __restrict__ Bhi, const __nv_bfloat16* __restrict__ Blo,
    const float* __restrict__ bias, float* __restrict__ outp, int mode)
{
    extern __shared__ __nv_bfloat16 sm2[];
    const uint32_t sb = smem_u32(sm2);   // slot s: A at s*32768, B at s*32768+16384

    const int tid = threadIdx.x, lane = tid & 31, wid = tid >> 5;
    const int m0 = blockIdx.x * 128, n0 = blockIdx.y * 128;
    const int lrow = tid >> 3;          // 0..15
    const int lcol = tid & 7;           // 16B chunk index in a 128B row

    const int wm = (wid & 1) * 64;
    const int wn = (wid >> 1) * 64;

    float c[4][8][4];
    #pragma unroll
    for (int a = 0; a < 4; a++)
        #pragma unroll
        for (int b = 0; b < 8; b++)
            #pragma unroll
            for (int d = 0; d < 4; d++) c[a][b][d] = 0.f;

    auto load_stage = [&](int kt, int slot) {
        const int seg = kt >> 4;
        const int kseg = (kt & 15) * 64;
        const __nv_bfloat16* As = (seg == 2) ? Alo : Ahi;
        const __nv_bfloat16* Bs = (seg == 1) ? Blo : Bhi;
        const uint32_t aBase = sb + slot * 32768;
        const uint32_t bBase = aBase + 16384;
        #pragma unroll
        for (int i = 0; i < 8; i++) {
            const int row = i * 16 + lrow;
            const uint32_t so = (uint32_t)(row * 128 + ((lcol ^ (row & 7)) << 4));
            cp16(aBase + so, As + (size_t)(m0 + row) * SDM + kseg + lcol * 8);
            cp16(bBase + so, Bs + (size_t)(n0 + row) * SDM + kseg + lcol * 8);
        }
        CP_COMMIT();
    };

    load_stage(0, 0);
    load_stage(1, 1);

    int slot = 0;
    for (int kt = 0; kt < KITER; kt++) {
        if (kt < KITER - 1) {
            asm volatile("cp.async.wait_group 1;" ::: "memory");
        } else {
            asm volatile("cp.async.wait_group 0;" ::: "memory");
        }
        __syncthreads();
        if (kt + 2 < KITER) {
            int ns = slot + 2; if (ns >= 3) ns -= 3;
            load_stage(kt + 2, ns);
        }

        const uint32_t aB = sb + slot * 32768;
        const uint32_t bB = aB + 16384;
        #pragma unroll
        for (int ks = 0; ks < 4; ks++) {
            const int kk = ks * 16;
            uint32_t a[4][4];
            #pragma unroll
            for (int mt = 0; mt < 4; mt++) {
                const int row = wm + mt * 16 + (lane & 15);
                const int kel = kk + ((lane >> 4) << 3);
                const uint32_t ad = aB + (uint32_t)(row * 128 + ((((kel >> 3) & 7) ^ (row & 7)) << 4));
                ldmx4(a[mt], ad);
            }
            uint32_t b[4][4];
            #pragma unroll
            for (int bt = 0; bt < 4; bt++) {
                const int nrow = wn + bt * 16 + (lane & 7) + ((lane >> 4) << 3);
                const int kel = kk + (((lane >> 3) & 1) << 3);
                const uint32_t bd = bB + (uint32_t)(nrow * 128 + ((((kel >> 3) & 7) ^ (nrow & 7)) << 4));
                ldmx4(b[bt], bd);
            }
            #pragma unroll
            for (int mt = 0; mt < 4; mt++)
                #pragma unroll
                for (int nt = 0; nt < 8; nt++)
                    mma16816(c[mt][nt], a[mt], b[nt >> 1] + 2 * (nt & 1));
        }
        if (++slot == 3) slot = 0;
    }

    // epilogue
    const int mrow = m0 + wm + (lane >> 2);
    const int ncol = n0 + wn + (lane & 3) * 2;
    #pragma unroll
    for (int mt = 0; mt < 4; mt++) {
        #pragma unroll
        for (int nt = 0; nt < 8; nt++) {
            const int nn = ncol + nt * 8;
            const float bx = bias[nn], by = bias[nn + 1];
            #pragma unroll
            for (int half = 0; half < 2; half++) {
                const int mm = mrow + mt * 16 + half * 8;
                float vx = c[mt][nt][half * 2 + 0] + bx;
                float vy = c[mt][nt][half * 2 + 1] + by;
                if (mode == 1) {
                    float2 o; o.x = vx; o.y = vy;
                    *(float2*)(outp + (size_t)mm * SDM + nn) = o;
                } else {
                    const int which = nn >> 10, h = (nn >> 6) & 15, d = nn & 63;
                    const int b = mm >> 11, s = mm & 2047;
                    const int bh = b * SH + h;
                    if (which == 0) { vx *= QSCALE; vy *= QSCALE; }
                    __nv_bfloat16 hx, lx, hy, ly;
                    split2(vx, hx, lx); split2(vy, hy, ly);
                    if (which == 2) {
                        const size_t i0 = ((size_t)bh * SD + d) * SS + s;
                        g_Vthi[i0] = hx; g_Vtlo[i0] = lx;
                        g_Vthi[i0 + SS] = hy; g_Vtlo[i0 + SS] = ly;
                    } else {
                        const size_t idx = ((size_t)bh * SS + s) * SD + d;
                        __nv_bfloat16* ph = (which == 0) ? g_Qhi : g_Khi;
                        __nv_bfloat16* pl = (which == 0) ? g_Qlo : g_Klo;
                        *(__nv_bfloat162*)(ph + idx) = __nv_bfloat162(hx, hy);
                        *(__nv_bfloat162*)(pl + idx) = __nv_bfloat162(lx, ly);
                    }
                }
            }
        }
    }
}

// ---------------------------------------------------------------------------
// tensor-core flash attention (validated in R4); epilogue -> AOhi/AOlo
// grid (16, 32): q-tile 128 x (b,h). 8 warps x 16 q-rows. K/V tile 64, 2 stages.
// ---------------------------------------------------------------------------
__global__ __launch_bounds__(256, 2) void attn_mma()
{
    extern __shared__ __nv_bfloat16 smA[];
    const uint32_t sQh = smem_u32(smA);
    const uint32_t sQl = sQh + 16384;
    const uint32_t sT  = sQl + 16384;   // stage st at sT + st*32768

    const int tid = threadIdx.x, lane = tid & 31, wid = tid >> 5;
    const int bh = blockIdx.y, q0 = blockIdx.x * 128;
    const __nv_bfloat16* Qh = g_Qhi + (size_t)bh * SS * SD;
    const __nv_bfloat16* Ql = g_Qlo + (size_t)bh * SS * SD;
    const __nv_bfloat16* Kh = g_Khi + (size_t)bh * SS * SD;
    const __nv_bfloat16* Kl = g_Klo + (size_t)bh * SS * SD;
    const __nv_bfloat16* Vh = g_Vthi + (size_t)bh * SD * SS;
    const __nv_bfloat16* Vl = g_Vtlo + (size_t)bh * SD * SS;

    {
        const int rq = tid >> 1, cb = (tid & 1) * 4;
        const __nv_bfloat16* ph = Qh + (size_t)(q0 + rq) * SD;
        const __nv_bfloat16* pl = Ql + (size_t)(q0 + rq) * SD;
        #pragma unroll
        for (int j = 0; j < 4; j++) {
            const uint32_t off = (uint32_t)(rq * 128 + (((cb + j) ^ (rq & 7)) << 4));
            cp16(sQh + off, ph + (cb + j) * 8);
            cp16(sQl + off, pl + (cb + j) * 8);
        }
    }

    const int r2 = tid >> 2, cb2 = (tid & 3) * 2;
    uint32_t toff[2];
    #pragma unroll
    for (int j = 0; j < 2; j++)
        toff[j] = (uint32_t)(r2 * 128 + (((cb2 + j) ^ (r2 & 7)) << 4));
    const __nv_bfloat16* pKh = Kh + (size_t)r2 * SD;
    const __nv_bfloat16* pKl = Kl + (size_t)r2 * SD;
    const __nv_bfloat16* pVh = Vh + (size_t)r2 * SS;
    const __nv_bfloat16* pVl = Vl + (size_t)r2 * SS;

    auto load_tile = [&](int itile, int st) {
        const uint32_t b0 = sT + st * 32768;
        const int t0 = itile * 64;
        #pragma unroll
        for (int j = 0; j < 2; j++) {
            cp16(b0 +         toff[j], pKh + (size_t)t0 * SD + (cb2 + j) * 8);
            cp16(b0 + 8192 +  toff[j], pKl + (size_t)t0 * SD + (cb2 + j) * 8);
            cp16(b0 + 16384 + toff[j], pVh + t0 + (cb2 + j) * 8);
            cp16(b0 + 24576 + toff[j], pVl + t0 + (cb2 + j) * 8);
        }
    };
    load_tile(0, 0);
    CP_COMMIT();

    float m0 = -1e30f, m1 = -1e30f, l0 = 0.f, l1 = 0.f;
    float o[8][4];
    #pragma unroll
    for (int f = 0; f < 8; f++)
        #pragma unroll
        for (int d = 0; d < 4; d++) o[f][d] = 0.f;

    for (int it = 0; it < 32; it++) {
        const int st = it & 1;
        if (it + 1 < 32) {
            load_tile(it + 1, st ^ 1);
            CP_COMMIT();
            asm volatile("cp.async.wait_group 1;" ::: "memory");
        } else {
            asm volatile("cp.async.wait_group 0;" ::: "memory");
        }
        __syncthreads();

        const uint32_t bKh = sT + st * 32768, bKl = bKh + 8192;
        const uint32_t bVh = bKh + 16384,    bVl = bKh + 24576;

        float c[8][4];
        #pragma unroll
        for (int f = 0; f < 8; f++)
            #pragma unroll
            for (int d = 0; d < 4; d++) c[f][d] = 0.f;

        #pragma unroll
        for (int ks = 0; ks < 4; ks++) {
            const int kk = ks * 16;
            uint32_t aQh[4], aQl[4];
            {
                const int row = wid * 16 + (lane & 15);
                const int kel = kk + ((lane >> 4) << 3);
                const uint32_t ao = (uint32_t)(row * 128 + ((((kel >> 3) & 7) ^ (row & 7)) << 4));
                ldmx4(aQh, sQh + ao);
                ldmx4(aQl, sQl + ao);
            }
            #pragma unroll
            for (int bt = 0; bt < 4; bt++) {
                const int nrow = bt * 16 + (lane & 7) + ((lane >> 4) << 3);
                const int kel = kk + (((lane >> 3) & 1) << 3);
                const uint32_t bo = (uint32_t)(nrow * 128 + ((((kel >> 3) & 7) ^ (nrow & 7)) << 4));
                uint32_t bKf[4], bLf[4];
                ldmx4(bKf, bKh + bo);
                ldmx4(bLf, bKl + bo);
                #pragma unroll
                for (int h2 = 0; h2 < 2; h2++) {
                    mma16816(c[bt * 2 + h2], aQh, bKf + 2 * h2);
                    mma16816(c[bt * 2 + h2], aQh, bLf + 2 * h2);
                    mma16816(c[bt * 2 + h2], aQl, bKf + 2 * h2);
                }
            }
        }

        float mx0 = -1e30f, mx1 = -1e30f;
        #pragma unroll
        for (int f = 0; f < 8; f++) {
            mx0 = fmaxf(mx0, fmaxf(c[f][0], c[f][1]));
            mx1 = fmaxf(mx1, fmaxf(c[f][2], c[f][3]));
        }
        mx0 = fmaxf(mx0, __shfl_xor_sync(0xffffffffu, mx0, 1));
        mx0 = fmaxf(mx0, __shfl_xor_sync(0xffffffffu, mx0, 2));
        mx1 = fmaxf(mx1, __shfl_xor_sync(0xffffffffu, mx1, 1));
        mx1 = fmaxf(mx1, __shfl_xor_sync(0xffffffffu, mx1, 2));
        const float mn0 = fmaxf(m0, mx0), mn1 = fmaxf(m1, mx1);
        const float corr0 = ex2(m0 - mn0), corr1 = ex2(m1 - mn1);
        m0 = mn0; m1 = mn1;

        uint32_t pA0[8], pA1[8], pL0[8], pL1[8];
        float rs0 = 0.f, rs1 = 0.f;
        #pragma unroll
        for (int f = 0; f < 8; f++) {
            const float p0 = ex2(c[f][0] - mn0), p1 = ex2(c[f][1] - mn0);
            const float p2 = ex2(c[f][2] - mn1), p3 = ex2(c[f][3] - mn1);
            rs0 += p0 + p1; rs1 += p2 + p3;
            __nv_bfloat16 h0, l0b, h1, l1b, h2b, l2b, h3, l3b;
            split2(p0, h0, l0b); split2(p1, h1, l1b);
            split2(p2, h2b, l2b); split2(p3, h3, l3b);
            pA0[f] = pack2(h0, h1);  pA1[f] = pack2(h2b, h3);
            pL0[f] = pack2(l0b, l1b); pL1[f] = pack2(l2b, l3b);
        }
        rs0 += __shfl_xor_sync(0xffffffffu, rs0, 1);
        rs0 += __shfl_xor_sync(0xffffffffu, rs0, 2);
        rs1 += __shfl_xor_sync(0xffffffffu, rs1, 1);
        rs1 += __shfl_xor_sync(0xffffffffu, rs1, 2);
        l0 = l0 * corr0 + rs0;
        l1 = l1 * corr1 + rs1;
        #pragma unroll
        for (int f = 0; f < 8; f++) {
            o[f][0] *= corr0; o[f][1] *= corr0;
            o[f][2] *= corr1; o[f][3] *= corr1;
        }

        #pragma unroll
        for (int tc = 0; tc < 4; tc++) {
            uint32_t aPh[4] = {pA0[2 * tc], pA1[2 * tc], pA0[2 * tc + 1], pA1[2 * tc + 1]};
            uint32_t aPl[4] = {pL0[2 * tc], pL1[2 * tc], pL0[2 * tc + 1], pL1[2 * tc + 1]};
            #pragma unroll
            for (int bt = 0; bt < 4; bt++) {
                const int nrow = bt * 16 + (lane & 7) + ((lane >> 4) << 3);
                const int kel = tc * 16 + (((lane >> 3) & 1) << 3);
                const uint32_t bo = (uint32_t)(nrow * 128 + ((((kel >> 3) & 7) ^ (nrow & 7)) << 4));
                uint32_t bVf[4], bWf[4];
                ldmx4(bVf, bVh + bo);
                ldmx4(bWf, bVl + bo);
                #pragma unroll
                for (int h2 = 0; h2 < 2; h2++) {
                    mma16816(o[bt * 2 + h2], aPh, bVf + 2 * h2);
                    mma16816(o[bt * 2 + h2], aPh, bWf + 2 * h2);
                    mma16816(o[bt * 2 + h2], aPl, bVf + 2 * h2);
                }
            }
        }
        __syncthreads();
    }

    // epilogue: write AO hi/lo for the proj GEMM
    const float inv0 = 1.f / l0, inv1 = 1.f / l1;
    const int b = bh >> 4, h = bh & 15;
    const int rr = lane >> 2, cc = (lane & 3) * 2;
    const int s0 = q0 + wid * 16 + rr;
    const size_t mrow0 = ((size_t)b * SS + s0) * SDM;
    const size_t mrow1 = mrow0 + (size_t)8 * SDM;
    #pragma unroll
    for (int f = 0; f < 8; f++) {
        const int kb = h * 64 + f * 8 + cc;
        {
            const float v0 = o[f][0] * inv0, v1 = o[f][1] * inv0;
            __nv_bfloat16 h0, l0b, h1, l1b;
            split2(v0, h0, l0b); split2(v1, h1, l1b);
            *(__nv_bfloat162*)(g_AOhi + mrow0 + kb) = __nv_bfloat162(h0, h1);
            *(__nv_bfloat162*)(g_AOlo + mrow0 + kb) = __nv_bfloat162(l0b, l1b);
        }
        {
            const float v0 = o[f][2] * inv1, v1 = o[f][3] * inv1;
            __nv_bfloat16 h0, l0b, h1, l1b;
            split2(v0, h0, l0b); split2(v1, h1, l1b);
            *(__nv_bfloat162*)(g_AOhi + mrow1 + kb) = __nv_bfloat162(h0, h1);
            *(__nv_bfloat162*)(g_AOlo + mrow1 + kb) = __nv_bfloat162(l0b, l1b);
        }
    }
}

// ---------------------------------------------------------------------------
extern "C" void kernel_launch(void* const* d_in, const int* in_sizes, int n_in,
                              void* d_out, int out_size)
{
    const float* x  = (const float*)d_in[0];
    const float* Wq = (const float*)d_in[1];
    const float* bq = (const float*)d_in[2];
    const float* Wk = (const float*)d_in[3];
    const float* bk = (const float*)d_in[4];
    const float* Wv = (const float*)d_in[5];
    const float* bv = (const float*)d_in[6];
    const float* Wo = (const float*)d_in[7];
    const float* bo = (const float*)d_in[8];
    float* out = (float*)d_out;

    __nv_bfloat16 *xhi, *xlo, *whi, *wlo, *wohi, *wolo, *aohi, *aolo;
    float *biasq;
    cudaGetSymbolAddress((void**)&xhi, g_Xhi);
    cudaGetSymbolAddress((void**)&xlo, g_Xlo);
    cudaGetSymbolAddress((void**)&whi, g_Whi);
    cudaGetSymbolAddress((void**)&wlo, g_Wlo);
    cudaGetSymbolAddress((void**)&wohi, g_Wohi);
    cudaGetSymbolAddress((void**)&wolo, g_Wolo);
    cudaGetSymbolAddress((void**)&aohi, g_AOhi);
    cudaGetSymbolAddress((void**)&aolo, g_AOlo);
    cudaGetSymbolAddress((void**)&biasq, g_bias_qkv);

    conv_x<<<512, 256>>>(x, xhi, xlo, MTOT * SDM);
    conv_wqkv<<<512, 256>>>(Wq, bq, Wk, bk, Wv, bv);
    conv_wo<<<256, 256>>>(Wo);

    const int gemm_smem = 98304;   // 3 stages x 32KB
    cudaFuncSetAttribute(hmma_gemm, cudaFuncAttributeMaxDynamicSharedMemorySize, gemm_smem);

    // QKV fused: [4096 x 3072 x 1024] x3 segments -> Q/K/Vt bf16 splits
    hmma_gemm<<<dim3(MTOT / 128, NQKV / 128), 128, gemm_smem>>>(
        xhi, xlo, whi, wlo, biasq, nullptr, 0);

    // tensor-core attention -> AOhi/AOlo
    const int attn_smem = 98304;
    cudaFuncSetAttribute(attn_mma, cudaFuncAttributeMaxDynamicSharedMemorySize, attn_smem);
    attn_mma<<<dim3(SS / 128, SB * SH), 256, attn_smem>>>();

    // proj: [4096 x 1024 x 1024] x3 segments
    hmma_gemm<<<dim3(MTOT / 128, SDM / 128), 128, gemm_smem>>>(
        aohi, aolo, wohi, wolo, bo, out, 1);
}